// round 17
// baseline (speedup 1.0000x reference)
#include <cuda_runtime.h>
#include <cuda_bf16.h>
#include <cstdint>

// input  [32, 64, 56, 56] fp32 -> zero-padded halo NHWC bf16 g_inq[32][58][58][64]
// weight [128, 64, 3, 3]  fp32 -> prequantized [kk][n][c] bf16 g_Wq
// output [32, 128, 56, 56] fp32
// Implicit GEMM (mma.sync bf16). BM=144 pixels; tiles may cross image
// boundaries (flat halo-row space makes the zero padding line up).
// 697 tiles -> max 5 tiles/SM (vs 6 with BM=128). Warp m-split 80/64.

#define HW 56
#define CIN 64
#define NOUT 128
#define PIX (HW*HW)            // 3136
#define MTOT (32*PIX)          // 100352
#define HLW 58
#define HPIX (HLW*HLW)         // 3364
#define BM 144
#define NTILES ((MTOT + BM - 1)/BM)   // 697
#define AROWSMAX 464           // 8 halo rows x 58 (worst case, crossing)
#define A_BYTES (AROWSMAX*128) // 59392
#define B_BYTES (NOUT*128)     // 16384
#define SMEM_ALLOC (A_BYTES + 3*B_BYTES)   // 108544
#define PADE 145               // epilogue float stride (>=144, odd)
#define PREP_IN_BLOCKS ((32*HPIX*4 + 255)/256)   // 1682

__device__ __align__(16) __nv_bfloat16 g_Wq[9 * NOUT * CIN];
__device__ __align__(16) __nv_bfloat16 g_inq[((size_t)32 * HPIX + 1024) * CIN]; // +slack

__device__ __forceinline__ uint32_t cvt2(float hi, float lo) {
    uint32_t r;
    asm("cvt.rn.bf16x2.f32 %0, %1, %2;" : "=r"(r) : "f"(hi), "f"(lo));
    return r;
}
__device__ __forceinline__ float ldcs(const float* p) {
    float v;
    asm("ld.global.cs.f32 %0, [%1];" : "=f"(v) : "l"(p));
    return v;
}

// Fused prep: blocks [0,288) quantize weights, rest build halo input
// (4 threads per halo pixel, 16 channels each -> coalesced 1KB/warp stores).
__global__ void prep_all(const float* __restrict__ w, const float* __restrict__ in) {
    if (blockIdx.x < 288) {
        int idx = blockIdx.x * 256 + threadIdx.x;   // 73728
        if (idx < 9 * NOUT * CIN) {
            int c  = idx & 63;
            int n  = (idx >> 6) & 127;
            int kk = idx >> 13;
            g_Wq[idx] = __float2bfloat16(w[(n * CIN + c) * 9 + kk]);
        }
        return;
    }
    int gid = (blockIdx.x - 288) * 256 + threadIdx.x;
    int pid = gid >> 2;                 // halo pixel
    int cg  = (gid & 3) * 16;           // channel group base
    if (pid >= 32 * HPIX) return;
    int b   = pid / HPIX;
    int rem = pid - b * HPIX;
    int hh  = rem / HLW;
    int ww  = rem - hh * HLW;
    __nv_bfloat16* dst = g_inq + (size_t)pid * CIN + cg;
    bool inside = (hh >= 1) && (hh <= HW) && (ww >= 1) && (ww <= HW);
    if (inside) {
        const float* src = in + ((size_t)b * CIN + cg) * PIX + (hh - 1) * HW + (ww - 1);
        float f[16];
#pragma unroll
        for (int j = 0; j < 16; j++) f[j] = ldcs(src + (size_t)j * PIX);
        uint4 v0, v1;
        v0.x = cvt2(f[1],  f[0]);  v0.y = cvt2(f[3],  f[2]);
        v0.z = cvt2(f[5],  f[4]);  v0.w = cvt2(f[7],  f[6]);
        v1.x = cvt2(f[9],  f[8]);  v1.y = cvt2(f[11], f[10]);
        v1.z = cvt2(f[13], f[12]); v1.w = cvt2(f[15], f[14]);
        *reinterpret_cast<uint4*>(dst)     = v0;
        *reinterpret_cast<uint4*>(dst + 8) = v1;
    } else {
        uint4 z = make_uint4(0, 0, 0, 0);
        *reinterpret_cast<uint4*>(dst)     = z;
        *reinterpret_cast<uint4*>(dst + 8) = z;
    }
}

__device__ __forceinline__ void cp16(uint32_t dst, const void* src) {
    asm volatile("cp.async.cg.shared.global [%0], [%1], 16;\n" :: "r"(dst), "l"(src));
}
__device__ __forceinline__ void ldmatrix_x4(uint32_t* r, uint32_t addr) {
    asm volatile("ldmatrix.sync.aligned.m8n8.x4.shared.b16 {%0,%1,%2,%3}, [%4];\n"
                 : "=r"(r[0]), "=r"(r[1]), "=r"(r[2]), "=r"(r[3]) : "r"(addr));
}
__device__ __forceinline__ void mma_bf16(float* c, const uint32_t* a, const uint32_t* b) {
    asm volatile("mma.sync.aligned.m16n8k16.row.col.f32.bf16.bf16.f32 "
                 "{%0,%1,%2,%3}, {%4,%5,%6,%7}, {%8,%9}, {%0,%1,%2,%3};\n"
                 : "+f"(c[0]), "+f"(c[1]), "+f"(c[2]), "+f"(c[3])
                 : "r"(a[0]), "r"(a[1]), "r"(a[2]), "r"(a[3]),
                   "r"(b[0]), "r"(b[1]));
}
__device__ __forceinline__ void stg_cs(float* p, float v) {
    asm volatile("st.global.cs.f32 [%0], %1;" :: "l"(p), "f"(v) : "memory");
}

__global__ __launch_bounds__(256, 2)
void qconv_mma(const float* __restrict__ bias, float* __restrict__ out) {
    extern __shared__ __align__(16) unsigned char dsm[];
    __shared__ float bias_s[NOUT];
    float* Ep = reinterpret_cast<float*>(dsm);

    const int tid  = threadIdx.x;
    const int lane = tid & 31;
    const int warp = tid >> 5;
    const int modd = warp & 1;                 // 0: rows 0-79 (MI=5); 1: rows 80-143 (MI=4)
    const int wm   = modd ? 80 : 0;
    const int MI   = modd ? 4 : 5;
    const int wn   = (warp >> 1) * 32;         // 0,32,64,96

    if (tid < NOUT) bias_s[tid] = __bfloat162float(__float2bfloat16(bias[tid]));

    // CTA geometry: global pixel tile [q0, q0+BM), may cross image boundaries
    const int q0 = blockIdx.x * BM;
    const int b0 = q0 / PIX;
    const int r0 = q0 - b0 * PIX;
    const int oh0 = r0 / HW;
    const int W0 = (b0 * HLW + oh0) * HLW;     // first flat halo pixel of window

    // window extent (flat halo pixels), <= AROWSMAX*... in halo pixels
    const int qe = min(q0 + BM - 1, MTOT - 1);
    const int be = qe / PIX;
    const int ohe = (qe - be * PIX) / HW;
    const int cnt_px = ((be * HLW + ohe + 3) - (b0 * HLW + oh0)) * HLW;  // <= 464

    const uint32_t smem_u32 = (uint32_t)__cvta_generic_to_shared(dsm);
    const uint32_t Ab = smem_u32;

    int rb[5];
#pragma unroll
    for (int mi = 0; mi < 5; mi++) {
        if (mi < MI) {
            int q = min(q0 + wm + mi * 16 + (lane & 15), MTOT - 1);
            int bq = q / PIX;
            int rq = q - bq * PIX;
            int ohq = rq / HW;
            int owq = rq - ohq * HW;
            rb[mi] = (bq * HLW + ohq) * HLW + owq - W0;
        }
    }

    float acc[5][4][4];
#pragma unroll
    for (int mi = 0; mi < 5; mi++)
#pragma unroll
        for (int ni = 0; ni < 4; ni++)
#pragma unroll
            for (int j = 0; j < 4; j++) acc[mi][ni][j] = 0.f;

    // ---- prologue: A window (cnt_px rows x 128B, SW128), one commit group ----
    const int ncp = cnt_px * 8;                // <= 3712
#pragma unroll
    for (int it = 0; it < 15; it++) {
        int idx = tid + it * 256;
        if (idx < ncp) {
            int row = idx >> 3, qc = idx & 7;
            uint32_t col = (uint32_t)(qc * 16) ^ (uint32_t)((row & 7) * 16);
            cp16(Ab + row * 128 + col, g_inq + ((size_t)W0 + row) * CIN + qc * 8);
        }
    }
    asm volatile("cp.async.commit_group;\n" ::: "memory");

    // B loader
    const int brow = tid >> 1, bhalf = tid & 1;
    const uint32_t bsw = (uint32_t)((brow & 7) * 16);
    auto issueB = [&](int kk, int s) {
        const __nv_bfloat16* srcB = g_Wq + kk * (NOUT * CIN) + brow * CIN + bhalf * 32;
        uint32_t dstB = smem_u32 + A_BYTES + (uint32_t)s * B_BYTES + (uint32_t)brow * 128;
#pragma unroll
        for (int j = 0; j < 4; j++)
            cp16(dstB + (((uint32_t)(bhalf * 64 + j * 16)) ^ bsw), srcB + j * 8);
        asm volatile("cp.async.commit_group;\n" ::: "memory");
    };

    issueB(0, 0);
    issueB(1, 1);

    // B fragment lane geometry
    uint32_t brow_l[2], bswl[2];
#pragma unroll
    for (int np = 0; np < 2; np++) {
        brow_l[np] = wn + np * 16 + (lane >> 4) * 8 + (lane & 7);
        bswl[np]   = (brow_l[np] & 7) * 16;
    }
    const uint32_t bcol_half = ((lane >> 3) & 1) * 16;
    const uint32_t acol0 = (uint32_t)((lane >> 4) * 16);

#pragma unroll 1
    for (int kk = 0; kk < 9; kk++) {
        if (kk < 8) asm volatile("cp.async.wait_group 1;\n" ::: "memory");
        else        asm volatile("cp.async.wait_group 0;\n" ::: "memory");
        __syncthreads();        // stage kk data visible; stage kk-1 reads done
        if (kk < 7) issueB(kk + 2, (kk + 2) % 3);

        const int kh = kk / 3, kw = kk - kh * 3;
        const int khw = kh * HLW + kw;
        const uint32_t bbase = smem_u32 + A_BYTES + (uint32_t)(kk % 3) * B_BYTES;

        uint32_t arow128[5], asw[5];
#pragma unroll
        for (int mi = 0; mi < 5; mi++) {
            if (mi < MI) {
                int ar = rb[mi] + khw;
                arow128[mi] = Ab + (uint32_t)ar * 128;
                asw[mi]     = (uint32_t)((ar & 7) * 16);
            }
        }

#pragma unroll
        for (int ks = 0; ks < 4; ks++) {
            const uint32_t ac = (uint32_t)(ks * 32) | acol0;
            uint32_t af[5][4];
#pragma unroll
            for (int mi = 0; mi < 5; mi++)
                if (mi < MI)
                    ldmatrix_x4(af[mi], arow128[mi] + (ac ^ asw[mi]));

            uint32_t bfr[4][2];
#pragma unroll
            for (int np = 0; np < 2; np++) {
                uint32_t bc = ((uint32_t)(ks * 32) | bcol_half) ^ bswl[np];
                uint32_t r4[4];
                ldmatrix_x4(r4, bbase + brow_l[np] * 128 + bc);
                bfr[np * 2][0] = r4[0]; bfr[np * 2][1] = r4[1];
                bfr[np * 2 + 1][0] = r4[2]; bfr[np * 2 + 1][1] = r4[3];
            }
#pragma unroll
            for (int mi = 0; mi < 5; mi++)
                if (mi < MI)
#pragma unroll
                    for (int ni = 0; ni < 4; ni++)
                        mma_bf16(acc[mi][ni], af[mi], bfr[ni]);
        }
    }
    __syncthreads();            // all stage-8 reads done before Ep overwrite

    // ---- epilogue: smem transpose, two 64-channel passes ----
    const int m_l  = tid & 127;
    const int half = tid >> 7;

#pragma unroll 1
    for (int p = 0; p < 2; p++) {
        if ((wn >> 6) == p) {
#pragma unroll
            for (int mi = 0; mi < 5; mi++) {
                if (mi < MI) {
#pragma unroll
                    for (int ni = 0; ni < 4; ni++) {
                        int ncol = (wn & 63) + ni * 8 + 2 * (lane & 3);
                        int mrow = wm + mi * 16 + (lane >> 2);
                        Ep[(ncol + 0) * PADE + mrow]     = acc[mi][ni][0];
                        Ep[(ncol + 1) * PADE + mrow]     = acc[mi][ni][1];
                        Ep[(ncol + 0) * PADE + mrow + 8] = acc[mi][ni][2];
                        Ep[(ncol + 1) * PADE + mrow + 8] = acc[mi][ni][3];
                    }
                }
            }
        }
        __syncthreads();
#pragma unroll 1
        for (int px = m_l; px < BM; px += 128) {
            int q = q0 + px;
            if (q < MTOT) {
                int bq = q / PIX;
                int rq = q - bq * PIX;
                float* ob = out + (size_t)bq * (NOUT * PIX) + rq;
#pragma unroll
                for (int i = 0; i < 32; i++) {
                    int n_l = half + 2 * i;
                    float v = Ep[n_l * PADE + px] + bias_s[p * 64 + n_l];
                    stg_cs(ob + (size_t)(p * 64 + n_l) * PIX, v);
                }
            }
        }
        __syncthreads();
    }
}

extern "C" void kernel_launch(void* const* d_in, const int* in_sizes, int n_in,
                              void* d_out, int out_size) {
    const float* inp    = (const float*)d_in[0];
    const float* weight = (const float*)d_in[1];
    const float* bias   = (const float*)d_in[2];
    float* out = (float*)d_out;
    (void)in_sizes; (void)n_in; (void)out_size;

    cudaFuncSetAttribute(qconv_mma, cudaFuncAttributeMaxDynamicSharedMemorySize, SMEM_ALLOC);

    prep_all<<<288 + PREP_IN_BLOCKS, 256>>>(weight, inp);
    qconv_mma<<<NTILES, 256, SMEM_ALLOC>>>(bias, out);
}